// round 14
// baseline (speedup 1.0000x reference)
#include <cuda_runtime.h>
#include <cuda_fp16.h>
#include <cstdint>

// ---------------- problem constants ----------------
#define MTOT 4096
#define NTOT 2048
#define KTOT 2048
#define BM   256
#define BN   128
#define BK   32
#define STAGES 4
#define KSTEPS (KTOT / BK)          // 64
#define THREADS 256

// fp16 smem stage row: 32 halves = 64B, permuted so each thread's fragment is LDS.128
#define ROWB 64
#define ASTG_A (BM * ROWB)          // 16384 per stage
#define ASTG_B (BN * ROWB)          // 8192  per stage

// ---------------- smem layout (bytes) ----------------
#define SM_BIAS 0
#define SM_GNW  512
#define SM_GNB  1024
#define SM_A    2048
#define SM_B    (SM_A + STAGES * ASTG_A)          // 67584
#define SMEM_TOTAL (SM_B + STAGES * ASTG_B)       // 100352 (98KB), 1 CTA/SM

// ---------------- PTX helpers ----------------
__device__ __forceinline__ uint32_t smem_u32(const void* p) {
    uint32_t a;
    asm("{ .reg .u64 t; cvta.to.shared.u64 t, %1; cvt.u32.u64 %0, t; }"
        : "=r"(a) : "l"(p));
    return a;
}

#define LDS128I(r0, r1, r2, r3, base, imm) \
    asm volatile("ld.shared.v4.u32 {%0, %1, %2, %3}, [%4+%5];" \
                 : "=r"(r0), "=r"(r1), "=r"(r2), "=r"(r3) : "r"(base), "n"(imm))

#define STS128I(base, imm, u0, u1, u2, u3) \
    asm volatile("st.shared.v4.u32 [%0+%1], {%2, %3, %4, %5};" \
                 :: "r"(base), "n"(imm), "r"(u0), "r"(u1), "r"(u2), "r"(u3) : "memory")

#define LDG64I(f0, f1, ptr, imm) \
    asm volatile("ld.global.nc.v2.f32 {%0, %1}, [%2+%3];" \
                 : "=f"(f0), "=f"(f1) : "l"(ptr), "n"(imm))

__device__ __forceinline__ void mma_f16(float* c, uint32_t a0, uint32_t a1,
                                        uint32_t a2, uint32_t a3,
                                        uint32_t b0, uint32_t b1) {
    asm volatile(
        "mma.sync.aligned.m16n8k16.row.col.f32.f16.f16.f32 "
        "{%0,%1,%2,%3}, {%4,%5,%6,%7}, {%8,%9}, {%0,%1,%2,%3};"
        : "+f"(c[0]), "+f"(c[1]), "+f"(c[2]), "+f"(c[3])
        : "r"(a0), "r"(a1), "r"(a2), "r"(a3), "r"(b0), "r"(b1));
}

// ---- conversion: one 16B fp16 chunk = 4 strided float2 loads + pack + STS.128 ----
// chunk (row, cT) covers permuted halves of one 32-col k-block:
//   h = {f(2c), f(2c+1), f(2c+8), f(2c+9), f(2c+16), f(2c+17), f(2c+24), f(2c+25)}
#define CLDG(fv, gp, GI)                        \
    LDG64I(fv[0], fv[1], gp, (GI) + 0);         \
    LDG64I(fv[2], fv[3], gp, (GI) + 32);        \
    LDG64I(fv[4], fv[5], gp, (GI) + 64);        \
    LDG64I(fv[6], fv[7], gp, (GI) + 96);

#define CSTS(fv, sbase, SI) do {                                     \
    __half2 h0 = __floats2half2_rn(fv[0], fv[1]);                    \
    __half2 h1 = __floats2half2_rn(fv[2], fv[3]);                    \
    __half2 h2 = __floats2half2_rn(fv[4], fv[5]);                    \
    __half2 h3 = __floats2half2_rn(fv[6], fv[7]);                    \
    STS128I(sbase, SI,                                               \
            *(const uint32_t*)&h0, *(const uint32_t*)&h1,            \
            *(const uint32_t*)&h2, *(const uint32_t*)&h3);           \
} while (0)

// A row-block step: 64 rows * 2048 f32 = 524288 bytes; smem 64 rows * 64B = 4096
#define GRB 524288
#define SRB 4096

// ---------------- kernel ----------------
__global__ void __launch_bounds__(THREADS, 1)
fused_linear_gn_ht_kernel(const float* __restrict__ x,
                          const float* __restrict__ w,
                          const float* __restrict__ bias,
                          const float* __restrict__ gnw,
                          const float* __restrict__ gnb,
                          float* __restrict__ out) {
    extern __shared__ char smem[];
    uint32_t sb = smem_u32(smem);
    int tid = threadIdx.x;
    int wid = tid >> 5, lid = tid & 31;
    int wm = wid >> 1, wn = wid & 1;           // warp grid 4 (M) x 2 (N), tile 64x64
    int gid = lid >> 2, tid4 = lid & 3;
    int bn = blockIdx.x, bm = blockIdx.y;

    float* bias_s = (float*)(smem + SM_BIAS);
    float* gnw_s  = (float*)(smem + SM_GNW);
    float* gnb_s  = (float*)(smem + SM_GNB);
    if (tid < BN) {
        bias_s[tid] = bias[bn * BN + tid];
        gnw_s[tid]  = gnw[bn * BN + tid];
        gnb_s[tid]  = gnb[bn * BN + tid];
    }

    // ---- conversion geometry: thread owns chunk (row rT(+64i), cT) of each stage
    int rT = tid >> 2, cT = tid & 3;
    const float* gA = x + ((size_t)bm * BM + rT) * KTOT + 2 * cT;
    const float* gB = w + ((size_t)bn * BN + rT) * KTOT + 2 * cT;
    uint32_t stsA = sb + SM_A + (uint32_t)(rT * ROWB + cT * 16);
    uint32_t stsB = sb + SM_B + (uint32_t)(rT * ROWB + cT * 16);

    // prologue: convert stages 0..2 (sequential, one-time)
#define PCH(gp, GI, sbase, SI) do { float fv[8]; CLDG(fv, gp, GI) CSTS(fv, sbase, SI); } while (0)
#define PRO(p)                                                        \
    PCH(gA, (p)*128 + 0*GRB, stsA, (p)*ASTG_A + 0*SRB);               \
    PCH(gA, (p)*128 + 1*GRB, stsA, (p)*ASTG_A + 1*SRB);               \
    PCH(gA, (p)*128 + 2*GRB, stsA, (p)*ASTG_A + 2*SRB);               \
    PCH(gA, (p)*128 + 3*GRB, stsA, (p)*ASTG_A + 3*SRB);               \
    PCH(gB, (p)*128 + 0*GRB, stsB, (p)*ASTG_B + 0*SRB);               \
    PCH(gB, (p)*128 + 1*GRB, stsB, (p)*ASTG_B + 1*SRB);
    PRO(0) PRO(1) PRO(2)
#undef PRO
#undef PCH
    gA += (STAGES - 1) * BK;
    gB += (STAGES - 1) * BK;

    float acc[4][8][4];
#pragma unroll
    for (int mi = 0; mi < 4; mi++)
#pragma unroll
        for (int ni = 0; ni < 8; ni++)
#pragma unroll
            for (int j = 0; j < 4; j++) acc[mi][ni][j] = 0.f;

    uint32_t aBase = sb + SM_A + (uint32_t)((wm * 64 + gid) * ROWB + tid4 * 16);
    uint32_t bBase = sb + SM_B + (uint32_t)((wn * 64 + gid) * ROWB + tid4 * 16);

#define LD_FRAGS(S)                                                              \
        LDS128I(alo[0][0], alo[0][1], alo[0][2], alo[0][3], aBase,               \
                (S) * ASTG_A + 0 * 1024);                                        \
        LDS128I(ahi[0][0], ahi[0][1], ahi[0][2], ahi[0][3], aBase,               \
                (S) * ASTG_A + 0 * 1024 + 512);                                  \
        LDS128I(alo[1][0], alo[1][1], alo[1][2], alo[1][3], aBase,               \
                (S) * ASTG_A + 1 * 1024);                                        \
        LDS128I(ahi[1][0], ahi[1][1], ahi[1][2], ahi[1][3], aBase,               \
                (S) * ASTG_A + 1 * 1024 + 512);                                  \
        LDS128I(alo[2][0], alo[2][1], alo[2][2], alo[2][3], aBase,               \
                (S) * ASTG_A + 2 * 1024);                                        \
        LDS128I(ahi[2][0], ahi[2][1], ahi[2][2], ahi[2][3], aBase,               \
                (S) * ASTG_A + 2 * 1024 + 512);                                  \
        LDS128I(alo[3][0], alo[3][1], alo[3][2], alo[3][3], aBase,               \
                (S) * ASTG_A + 3 * 1024);                                        \
        LDS128I(ahi[3][0], ahi[3][1], ahi[3][2], ahi[3][3], aBase,               \
                (S) * ASTG_A + 3 * 1024 + 512);                                  \
        LDS128I(bfr[0][0], bfr[0][1], bfr[0][2], bfr[0][3], bBase,               \
                (S) * ASTG_B + 0 * 512);                                         \
        LDS128I(bfr[1][0], bfr[1][1], bfr[1][2], bfr[1][3], bBase,               \
                (S) * ASTG_B + 1 * 512);                                         \
        LDS128I(bfr[2][0], bfr[2][1], bfr[2][2], bfr[2][3], bBase,               \
                (S) * ASTG_B + 2 * 512);                                         \
        LDS128I(bfr[3][0], bfr[3][1], bfr[3][2], bfr[3][3], bBase,               \
                (S) * ASTG_B + 3 * 512);                                         \
        LDS128I(bfr[4][0], bfr[4][1], bfr[4][2], bfr[4][3], bBase,               \
                (S) * ASTG_B + 4 * 512);                                         \
        LDS128I(bfr[5][0], bfr[5][1], bfr[5][2], bfr[5][3], bBase,               \
                (S) * ASTG_B + 5 * 512);                                         \
        LDS128I(bfr[6][0], bfr[6][1], bfr[6][2], bfr[6][3], bBase,               \
                (S) * ASTG_B + 6 * 512);                                         \
        LDS128I(bfr[7][0], bfr[7][1], bfr[7][2], bfr[7][3], bBase,               \
                (S) * ASTG_B + 7 * 512);

#define MMA_Q(BLK, M0)                                                           \
        _Pragma("unroll")                                                        \
        for (int mi = (M0); mi < (M0) + 2; mi++)                                 \
            _Pragma("unroll")                                                    \
            for (int ni = 0; ni < 8; ni++)                                       \
                mma_f16(acc[mi][ni],                                             \
                        alo[mi][(BLK) * 2 + 0], ahi[mi][(BLK) * 2 + 0],          \
                        alo[mi][(BLK) * 2 + 1], ahi[mi][(BLK) * 2 + 1],          \
                        bfr[ni][(BLK) * 2 + 0], bfr[ni][(BLK) * 2 + 1]);

// k-step: barrier; prefetch-convert stage PS interleaved between MMA quarters
#define KITER(S)                                                                 \
    do {                                                                         \
        __syncthreads();                                                         \
        constexpr int PS = ((S) + STAGES - 1) & (STAGES - 1);                    \
        const bool pf = (ks0 + (S) + STAGES - 1 < KSTEPS);                       \
        float fa0[8], fa1[8], fa2[8], fa3[8], fb0[8], fb1[8];                    \
        if (pf) { CLDG(fa0, gA, (S) * 128 + 0 * GRB)                             \
                  CLDG(fa1, gA, (S) * 128 + 1 * GRB) }                           \
        uint32_t alo[4][4], ahi[4][4], bfr[8][4];                                \
        LD_FRAGS(S)                                                              \
        MMA_Q(0, 0)                                                              \
        if (pf) { CSTS(fa0, stsA, PS * ASTG_A + 0 * SRB);                        \
                  CSTS(fa1, stsA, PS * ASTG_A + 1 * SRB);                        \
                  CLDG(fa2, gA, (S) * 128 + 2 * GRB)                             \
                  CLDG(fa3, gA, (S) * 128 + 3 * GRB) }                           \
        MMA_Q(0, 2)                                                              \
        if (pf) { CSTS(fa2, stsA, PS * ASTG_A + 2 * SRB);                        \
                  CSTS(fa3, stsA, PS * ASTG_A + 3 * SRB);                        \
                  CLDG(fb0, gB, (S) * 128 + 0 * GRB)                             \
                  CLDG(fb1, gB, (S) * 128 + 1 * GRB) }                           \
        MMA_Q(1, 0)                                                              \
        if (pf) { CSTS(fb0, stsB, PS * ASTG_B + 0 * SRB);                        \
                  CSTS(fb1, stsB, PS * ASTG_B + 1 * SRB); }                      \
        MMA_Q(1, 2)                                                              \
    } while (0)

    for (int ks0 = 0; ks0 < KSTEPS; ks0 += STAGES) {
        KITER(0);
        KITER(1);
        KITER(2);
        KITER(3);
        gA += STAGES * BK;            // one bump per 4 k-steps (128 floats)
        gB += STAGES * BK;
    }
#undef KITER
#undef MMA_Q
#undef LD_FRAGS

    // ---------------- fused epilogue: bias + GroupNorm(64) + hardtanh ----------------
    int gcol = wn * 64;
    size_t gout = (size_t)bn * BN + gcol;

#pragma unroll
    for (int mi = 0; mi < 4; mi++) {
#pragma unroll
        for (int half = 0; half < 2; half++) {
            int row_l = wm * 64 + mi * 16 + half * 8 + gid;
            float sum = 0.f, ssq = 0.f;
            float v[8][2];
#pragma unroll
            for (int ni = 0; ni < 8; ni++) {
                int c = ni * 8 + 2 * tid4;
                float v0 = acc[mi][ni][half * 2 + 0] + bias_s[gcol + c + 0];
                float v1 = acc[mi][ni][half * 2 + 1] + bias_s[gcol + c + 1];
                v[ni][0] = v0; v[ni][1] = v1;
                sum += v0 + v1;
                ssq += v0 * v0 + v1 * v1;
            }
            sum += __shfl_xor_sync(0xffffffffu, sum, 1);
            ssq += __shfl_xor_sync(0xffffffffu, ssq, 1);
            sum += __shfl_xor_sync(0xffffffffu, sum, 2);
            ssq += __shfl_xor_sync(0xffffffffu, ssq, 2);

            float mean = sum * (1.f / 64.f);
            float var  = ssq * (1.f / 64.f) - mean * mean;
            float inv  = rsqrtf(var + 1e-5f);

            size_t orow = (size_t)(bm * BM + row_l) * NTOT + gout;
#pragma unroll
            for (int ni = 0; ni < 8; ni++) {
                int c = ni * 8 + 2 * tid4;
                float2 o;
                o.x = fminf(fmaxf((v[ni][0] - mean) * inv * gnw_s[gcol + c + 0]
                                  + gnb_s[gcol + c + 0], -1.f), 1.f);
                o.y = fminf(fmaxf((v[ni][1] - mean) * inv * gnw_s[gcol + c + 1]
                                  + gnb_s[gcol + c + 1], -1.f), 1.f);
                *(float2*)(out + orow + c) = o;
            }
        }
    }
}

// ---------------- launch ----------------
extern "C" void kernel_launch(void* const* d_in, const int* in_sizes, int n_in,
                              void* d_out, int out_size) {
    const float* x    = (const float*)d_in[0];
    const float* w    = (const float*)d_in[1];
    const float* bias = (const float*)d_in[2];
    const float* gnw  = (const float*)d_in[3];
    const float* gnb  = (const float*)d_in[4];
    float* out = (float*)d_out;

    static bool attr_done = false;
    if (!attr_done) {
        cudaFuncSetAttribute(fused_linear_gn_ht_kernel,
                             cudaFuncAttributeMaxDynamicSharedMemorySize, SMEM_TOTAL);
        attr_done = true;
    }

    dim3 grid(NTOT / BN, MTOT / BM);   // (16, 16) = 256 CTAs, single kernel
    fused_linear_gn_ht_kernel<<<grid, THREADS, SMEM_TOTAL>>>(x, w, bias, gnw, gnb, out);
}

// round 15
// speedup vs baseline: 3.1217x; 3.1217x over previous
#include <cuda_runtime.h>
#include <cuda_fp16.h>
#include <cstdint>

// ---------------- problem constants ----------------
#define MTOT 4096
#define NTOT 2048
#define KTOT 2048
#define BM   256
#define BN   128
#define BK   32
#define STAGES 8
#define KSTEPS (KTOT / BK)          // 64
#define THREADS 256

// fp16 smem stage row: 32 halves = 64B, permuted so each thread's fragment is LDS.128
#define ROWB 64
#define ASTG_A (BM * ROWB)          // 16384 bytes per A stage
#define ASTG_B (BN * ROWB)          // 8192  bytes per B stage

// ---------------- smem layout (bytes) ----------------
#define SM_BIAS 0
#define SM_GNW  512
#define SM_GNB  1024
#define SM_A    2048
#define SM_B    (SM_A + STAGES * ASTG_A)          // 133120
#define SMEM_TOTAL (SM_B + STAGES * ASTG_B)       // 198656 (194KB), 1 CTA/SM

// ---------------- fp16, fragment-permuted scratch ----------------
__device__ __half g_xsh[(size_t)MTOT * KTOT];   // 16 MB
__device__ __half g_wsh[(size_t)NTOT * KTOT];   //  8 MB

// ---------------- PTX helpers ----------------
__device__ __forceinline__ uint32_t smem_u32(const void* p) {
    uint32_t a;
    asm("{ .reg .u64 t; cvta.to.shared.u64 t, %1; cvt.u32.u64 %0, t; }"
        : "=r"(a) : "l"(p));
    return a;
}

#define CP_A16I(smreg, gptr, smimm, gimm) \
    asm volatile("cp.async.cg.shared.global [%0+%2], [%1+%3], 16;" \
                 :: "r"(smreg), "l"(gptr), "n"(smimm), "n"(gimm) : "memory")
#define CP_COMMIT() asm volatile("cp.async.commit_group;" ::: "memory")
#define CP_WAIT(n)  asm volatile("cp.async.wait_group %0;" :: "n"(n) : "memory")

#define LDS128I(r0, r1, r2, r3, base, imm) \
    asm volatile("ld.shared.v4.u32 {%0, %1, %2, %3}, [%4+%5];" \
                 : "=r"(r0), "=r"(r1), "=r"(r2), "=r"(r3) : "r"(base), "n"(imm))

__device__ __forceinline__ void mma_f16(float* c, uint32_t a0, uint32_t a1,
                                        uint32_t a2, uint32_t a3,
                                        uint32_t b0, uint32_t b1) {
    asm volatile(
        "mma.sync.aligned.m16n8k16.row.col.f32.f16.f16.f32 "
        "{%0,%1,%2,%3}, {%4,%5,%6,%7}, {%8,%9}, {%0,%1,%2,%3};"
        : "+f"(c[0]), "+f"(c[1]), "+f"(c[2]), "+f"(c[3])
        : "r"(a0), "r"(a1), "r"(a2), "r"(a3), "r"(b0), "r"(b1));
}

// ---------------- prepass: fp32 -> fp16 + fragment permutation ----------------
__global__ void __launch_bounds__(256)
prepass_kernel(const float* __restrict__ x, const float* __restrict__ w, int nunit) {
    int u = blockIdx.x * 256 + threadIdx.x;
    if (u >= nunit) return;
    int row = u >> 6;
    int uc  = u & 63;
    const float* src;
    __half* dst;
    if (row < MTOT) {
        src = x + (size_t)row * KTOT + uc * 32;
        dst = g_xsh + (size_t)row * KTOT + uc * 32;
    } else {
        src = w + (size_t)(row - MTOT) * KTOT + uc * 32;
        dst = g_wsh + (size_t)(row - MTOT) * KTOT + uc * 32;
    }
    float v[32];
#pragma unroll
    for (int i = 0; i < 8; i++) {
        float4 f = ((const float4*)src)[i];
        v[i * 4 + 0] = f.x; v[i * 4 + 1] = f.y; v[i * 4 + 2] = f.z; v[i * 4 + 3] = f.w;
    }
    __half h[32];
#pragma unroll
    for (int t4 = 0; t4 < 4; t4++) {
#pragma unroll
        for (int blk = 0; blk < 2; blk++) {
            int o = t4 * 8 + blk * 4;
            int c = blk * 16 + 2 * t4;
            h[o + 0] = __float2half_rn(v[c + 0]);
            h[o + 1] = __float2half_rn(v[c + 1]);
            h[o + 2] = __float2half_rn(v[c + 8]);
            h[o + 3] = __float2half_rn(v[c + 9]);
        }
    }
#pragma unroll
    for (int i = 0; i < 4; i++)
        ((uint4*)dst)[i] = ((const uint4*)h)[i];
}

// ---------------- kernel ----------------
__global__ void __launch_bounds__(THREADS, 1)
fused_linear_gn_ht_kernel(const __half* __restrict__ xs,
                          const __half* __restrict__ ws,
                          const float* __restrict__ bias,
                          const float* __restrict__ gnw,
                          const float* __restrict__ gnb,
                          float* __restrict__ out) {
    extern __shared__ char smem[];
    uint32_t sb = smem_u32(smem);
    int tid = threadIdx.x;
    int wid = tid >> 5, lid = tid & 31;
    int wm = wid >> 1, wn = wid & 1;           // warp grid 4 (M) x 2 (N), tile 64x64
    int gid = lid >> 2, tid4 = lid & 3;
    int bn = blockIdx.x, bm = blockIdx.y;

    float* bias_s = (float*)(smem + SM_BIAS);
    float* gnw_s  = (float*)(smem + SM_GNW);
    float* gnb_s  = (float*)(smem + SM_GNB);
    if (tid < BN) {
        bias_s[tid] = bias[bn * BN + tid];
        gnw_s[tid]  = gnw[bn * BN + tid];
        gnb_s[tid]  = gnb[bn * BN + tid];
    }

    // ---- cp.async geometry: r = tid>>2 (+64 per i), c = tid&3
    int rA = tid >> 2, cA = tid & 3;
    uint32_t cpA = sb + SM_A + (uint32_t)(rA * ROWB + cA * 16);
    uint32_t cpB = sb + SM_B + (uint32_t)(rA * ROWB + cA * 16);
    const __half* aPtr = xs + (size_t)bm * BM * KTOT + (size_t)rA * KTOT + cA * 8;
    const __half* bPtr = ws + (size_t)bn * BN * KTOT + (size_t)rA * KTOT + cA * 8;
    // +64 rows: global +64*KTOT*2 = 262144 bytes; smem +64*ROWB = 4096 bytes
#define GCH 262144
#define SCH 4096

    // prologue: stages 0..6 (A: 4 chunks/thread, B: 2 chunks/thread)
#define PRO(p) do {                                                       \
        CP_A16I(cpA, aPtr, (p) * ASTG_A + 0 * SCH, (p) * 64 + 0 * GCH);   \
        CP_A16I(cpA, aPtr, (p) * ASTG_A + 1 * SCH, (p) * 64 + 1 * GCH);   \
        CP_A16I(cpA, aPtr, (p) * ASTG_A + 2 * SCH, (p) * 64 + 2 * GCH);   \
        CP_A16I(cpA, aPtr, (p) * ASTG_A + 3 * SCH, (p) * 64 + 3 * GCH);   \
        CP_A16I(cpB, bPtr, (p) * ASTG_B + 0 * SCH, (p) * 64 + 0 * GCH);   \
        CP_A16I(cpB, bPtr, (p) * ASTG_B + 1 * SCH, (p) * 64 + 1 * GCH);   \
        CP_COMMIT();                                                      \
    } while (0)
    PRO(0); PRO(1); PRO(2); PRO(3); PRO(4); PRO(5); PRO(6);
#undef PRO
    aPtr += (STAGES - 1) * BK;
    bPtr += (STAGES - 1) * BK;

    float acc[4][8][4];
#pragma unroll
    for (int mi = 0; mi < 4; mi++)
#pragma unroll
        for (int ni = 0; ni < 8; ni++)
#pragma unroll
            for (int j = 0; j < 4; j++) acc[mi][ni][j] = 0.f;

    // fragment base addresses (2 registers; everything else immediate)
    uint32_t aBase = sb + SM_A + (uint32_t)((wm * 64 + gid) * ROWB + tid4 * 16);
    uint32_t bBase = sb + SM_B + (uint32_t)((wn * 64 + gid) * ROWB + tid4 * 16);

    // ---- fully expanded fragment loads (literal immediates only) ----
#define LD_FRAGS(S)                                                              \
        LDS128I(alo[0][0], alo[0][1], alo[0][2], alo[0][3], aBase,               \
                (S) * ASTG_A + 0 * 1024);                                        \
        LDS128I(ahi[0][0], ahi[0][1], ahi[0][2], ahi[0][3], aBase,               \
                (S) * ASTG_A + 0 * 1024 + 512);                                  \
        LDS128I(alo[1][0], alo[1][1], alo[1][2], alo[1][3], aBase,               \
                (S) * ASTG_A + 1 * 1024);                                        \
        LDS128I(ahi[1][0], ahi[1][1], ahi[1][2], ahi[1][3], aBase,               \
                (S) * ASTG_A + 1 * 1024 + 512);                                  \
        LDS128I(alo[2][0], alo[2][1], alo[2][2], alo[2][3], aBase,               \
                (S) * ASTG_A + 2 * 1024);                                        \
        LDS128I(ahi[2][0], ahi[2][1], ahi[2][2], ahi[2][3], aBase,               \
                (S) * ASTG_A + 2 * 1024 + 512);                                  \
        LDS128I(alo[3][0], alo[3][1], alo[3][2], alo[3][3], aBase,               \
                (S) * ASTG_A + 3 * 1024);                                        \
        LDS128I(ahi[3][0], ahi[3][1], ahi[3][2], ahi[3][3], aBase,               \
                (S) * ASTG_A + 3 * 1024 + 512);                                  \
        LDS128I(bfr[0][0], bfr[0][1], bfr[0][2], bfr[0][3], bBase,               \
                (S) * ASTG_B + 0 * 512);                                         \
        LDS128I(bfr[1][0], bfr[1][1], bfr[1][2], bfr[1][3], bBase,               \
                (S) * ASTG_B + 1 * 512);                                         \
        LDS128I(bfr[2][0], bfr[2][1], bfr[2][2], bfr[2][3], bBase,               \
                (S) * ASTG_B + 2 * 512);                                         \
        LDS128I(bfr[3][0], bfr[3][1], bfr[3][2], bfr[3][3], bBase,               \
                (S) * ASTG_B + 3 * 512);                                         \
        LDS128I(bfr[4][0], bfr[4][1], bfr[4][2], bfr[4][3], bBase,               \
                (S) * ASTG_B + 4 * 512);                                         \
        LDS128I(bfr[5][0], bfr[5][1], bfr[5][2], bfr[5][3], bBase,               \
                (S) * ASTG_B + 5 * 512);                                         \
        LDS128I(bfr[6][0], bfr[6][1], bfr[6][2], bfr[6][3], bBase,               \
                (S) * ASTG_B + 6 * 512);                                         \
        LDS128I(bfr[7][0], bfr[7][1], bfr[7][2], bfr[7][3], bBase,               \
                (S) * ASTG_B + 7 * 512);

#define KITER(S)                                                                 \
    do {                                                                         \
        CP_WAIT(STAGES - 2);                                                     \
        __syncthreads();                                                         \
        if (k0 + (S) + STAGES - 1 < KSTEPS) {                                    \
            constexpr int PS = ((S) + STAGES - 1) & (STAGES - 1);                \
            CP_A16I(cpA, aPtr, PS * ASTG_A + 0 * SCH, (S) * 64 + 0 * GCH);       \
            CP_A16I(cpA, aPtr, PS * ASTG_A + 1 * SCH, (S) * 64 + 1 * GCH);       \
            CP_A16I(cpA, aPtr, PS * ASTG_A + 2 * SCH, (S) * 64 + 2 * GCH);       \
            CP_A16I(cpA, aPtr, PS * ASTG_A + 3 * SCH, (S) * 64 + 3 * GCH);       \
            CP_A16I(cpB, bPtr, PS * ASTG_B + 0 * SCH, (S) * 64 + 0 * GCH);       \
            CP_A16I(cpB, bPtr, PS * ASTG_B + 1 * SCH, (S) * 64 + 1 * GCH);       \
        }                                                                        \
        CP_COMMIT();                                                             \
        uint32_t alo[4][4], ahi[4][4], bfr[8][4];                                \
        LD_FRAGS(S)                                                              \
        _Pragma("unroll")                                                        \
        for (int blk = 0; blk < 2; blk++)                                        \
            _Pragma("unroll")                                                    \
            for (int mi = 0; mi < 4; mi++)                                       \
                _Pragma("unroll")                                                \
                for (int ni = 0; ni < 8; ni++)                                   \
                    mma_f16(acc[mi][ni],                                         \
                            alo[mi][blk * 2 + 0], ahi[mi][blk * 2 + 0],          \
                            alo[mi][blk * 2 + 1], ahi[mi][blk * 2 + 1],          \
                            bfr[ni][blk * 2 + 0], bfr[ni][blk * 2 + 1]);         \
    } while (0)

    for (int k0 = 0; k0 < KSTEPS; k0 += STAGES) {
        KITER(0);
        KITER(1);
        KITER(2);
        KITER(3);
        KITER(4);
        KITER(5);
        KITER(6);
        KITER(7);
        aPtr += STAGES * BK;          // one bump per 8 k-steps
        bPtr += STAGES * BK;
    }
#undef KITER
#undef LD_FRAGS

    // ---------------- fused epilogue: bias + GroupNorm(64) + hardtanh ----------------
    int gcol = wn * 64;
    size_t gout = (size_t)bn * BN + gcol;

#pragma unroll
    for (int mi = 0; mi < 4; mi++) {
#pragma unroll
        for (int half = 0; half < 2; half++) {
            int row_l = wm * 64 + mi * 16 + half * 8 + gid;
            float sum = 0.f, ssq = 0.f;
            float v[8][2];
#pragma unroll
            for (int ni = 0; ni < 8; ni++) {
                int c = ni * 8 + 2 * tid4;
                float v0 = acc[mi][ni][half * 2 + 0] + bias_s[gcol + c + 0];
                float v1 = acc[mi][ni][half * 2 + 1] + bias_s[gcol + c + 1];
                v[ni][0] = v0; v[ni][1] = v1;
                sum += v0 + v1;
                ssq += v0 * v0 + v1 * v1;
            }
            sum += __shfl_xor_sync(0xffffffffu, sum, 1);
            ssq += __shfl_xor_sync(0xffffffffu, ssq, 1);
            sum += __shfl_xor_sync(0xffffffffu, sum, 2);
            ssq += __shfl_xor_sync(0xffffffffu, ssq, 2);

            float mean = sum * (1.f / 64.f);
            float var  = ssq * (1.f / 64.f) - mean * mean;
            float inv  = rsqrtf(var + 1e-5f);

            size_t orow = (size_t)(bm * BM + row_l) * NTOT + gout;
#pragma unroll
            for (int ni = 0; ni < 8; ni++) {
                int c = ni * 8 + 2 * tid4;
                float2 o;
                o.x = fminf(fmaxf((v[ni][0] - mean) * inv * gnw_s[gcol + c + 0]
                                  + gnb_s[gcol + c + 0], -1.f), 1.f);
                o.y = fminf(fmaxf((v[ni][1] - mean) * inv * gnw_s[gcol + c + 1]
                                  + gnb_s[gcol + c + 1], -1.f), 1.f);
                *(float2*)(out + orow + c) = o;
            }
        }
    }
}

// ---------------- launch ----------------
extern "C" void kernel_launch(void* const* d_in, const int* in_sizes, int n_in,
                              void* d_out, int out_size) {
    const float* x    = (const float*)d_in[0];
    const float* w    = (const float*)d_in[1];
    const float* bias = (const float*)d_in[2];
    const float* gnw  = (const float*)d_in[3];
    const float* gnb  = (const float*)d_in[4];
    float* out = (float*)d_out;

    static bool attr_done = false;
    if (!attr_done) {
        cudaFuncSetAttribute(fused_linear_gn_ht_kernel,
                             cudaFuncAttributeMaxDynamicSharedMemorySize, SMEM_TOTAL);
        attr_done = true;
    }

    __half* xs; __half* ws;
    cudaGetSymbolAddress((void**)&xs, g_xsh);
    cudaGetSymbolAddress((void**)&ws, g_wsh);

    int nunit = ((MTOT + NTOT) * KTOT) / 32;    // 393216
    prepass_kernel<<<(nunit + 255) / 256, 256>>>(x, w, nunit);

    dim3 grid(NTOT / BN, MTOT / BM);   // (16, 16) = 256 CTAs
    fused_linear_gn_ht_kernel<<<grid, THREADS, SMEM_TOTAL>>>(xs, ws, bias, gnw, gnb, out);
}

// round 16
// speedup vs baseline: 3.1680x; 1.0148x over previous
#include <cuda_runtime.h>
#include <cuda_fp16.h>
#include <cstdint>

// ---------------- problem constants ----------------
#define MTOT 4096
#define NTOT 2048
#define KTOT 2048
#define BM   256
#define BN   128
#define BK   32
#define STAGES 8
#define KSTEPS (KTOT / BK)          // 64
#define THREADS 256
#define NBLOCKS 148                 // persistent CTAs; 194KB smem -> 1/SM, 148 <= 152 SMs
#define NTILES ((MTOT / BM) * (NTOT / BN))   // 256
#define NUNIT (((MTOT + NTOT) * KTOT) / 32)  // 393216 convert units

// fp16 smem stage row: 32 halves = 64B, permuted so each thread's fragment is LDS.128
#define ROWB 64
#define ASTG_A (BM * ROWB)          // 16384 bytes per A stage
#define ASTG_B (BN * ROWB)          // 8192  bytes per B stage

// ---------------- smem layout (bytes) ----------------
#define SM_BIAS 0
#define SM_GNW  512
#define SM_GNB  1024
#define SM_A    2048
#define SM_B    (SM_A + STAGES * ASTG_A)          // 133120
#define SMEM_TOTAL (SM_B + STAGES * ASTG_B)       // 198656 (194KB), 1 CTA/SM

// ---------------- fp16, fragment-permuted scratch + grid barrier ----------------
__device__ __half g_xsh[(size_t)MTOT * KTOT];   // 16 MB
__device__ __half g_wsh[(size_t)NTOT * KTOT];   //  8 MB
__device__ unsigned int g_bar_count = 0;
__device__ unsigned int g_bar_gen   = 0;

// ---------------- PTX helpers ----------------
__device__ __forceinline__ uint32_t smem_u32(const void* p) {
    uint32_t a;
    asm("{ .reg .u64 t; cvta.to.shared.u64 t, %1; cvt.u32.u64 %0, t; }"
        : "=r"(a) : "l"(p));
    return a;
}

#define CP_A16I(smreg, gptr, smimm, gimm) \
    asm volatile("cp.async.cg.shared.global [%0+%2], [%1+%3], 16;" \
                 :: "r"(smreg), "l"(gptr), "n"(smimm), "n"(gimm) : "memory")
#define CP_COMMIT() asm volatile("cp.async.commit_group;" ::: "memory")
#define CP_WAIT(n)  asm volatile("cp.async.wait_group %0;" :: "n"(n) : "memory")

#define LDS128I(r0, r1, r2, r3, base, imm) \
    asm volatile("ld.shared.v4.u32 {%0, %1, %2, %3}, [%4+%5];" \
                 : "=r"(r0), "=r"(r1), "=r"(r2), "=r"(r3) : "r"(base), "n"(imm))

__device__ __forceinline__ void mma_f16(float* c, uint32_t a0, uint32_t a1,
                                        uint32_t a2, uint32_t a3,
                                        uint32_t b0, uint32_t b1) {
    asm volatile(
        "mma.sync.aligned.m16n8k16.row.col.f32.f16.f16.f32 "
        "{%0,%1,%2,%3}, {%4,%5,%6,%7}, {%8,%9}, {%0,%1,%2,%3};"
        : "+f"(c[0]), "+f"(c[1]), "+f"(c[2]), "+f"(c[3])
        : "r"(a0), "r"(a1), "r"(a2), "r"(a3), "r"(b0), "r"(b1));
}

// ---------------- kernel ----------------
__global__ void __launch_bounds__(THREADS, 1)
fused_linear_gn_ht_kernel(const float* __restrict__ x,
                          const float* __restrict__ w,
                          const float* __restrict__ bias,
                          const float* __restrict__ gnw,
                          const float* __restrict__ gnb,
                          float* __restrict__ out) {
    extern __shared__ char smem[];
    uint32_t sb = smem_u32(smem);
    int tid = threadIdx.x;
    int wid = tid >> 5, lid = tid & 31;
    int wm = wid >> 1, wn = wid & 1;           // warp grid 4 (M) x 2 (N), tile 64x64
    int gid = lid >> 2, tid4 = lid & 3;

    // ======== phase 1: fp32 -> fp16 convert + fragment permutation (grid-strided) ========
    for (int u = blockIdx.x * THREADS + tid; u < NUNIT; u += NBLOCKS * THREADS) {
        int row = u >> 6;                  // 64 units of 32 cols per 2048-col row
        int uc  = u & 63;
        const float* src;
        __half* dst;
        if (row < MTOT) {
            src = x + (size_t)row * KTOT + uc * 32;
            dst = g_xsh + (size_t)row * KTOT + uc * 32;
        } else {
            src = w + (size_t)(row - MTOT) * KTOT + uc * 32;
            dst = g_wsh + (size_t)(row - MTOT) * KTOT + uc * 32;
        }
        float v[32];
#pragma unroll
        for (int i = 0; i < 8; i++) {
            float4 f = ((const float4*)src)[i];
            v[i * 4 + 0] = f.x; v[i * 4 + 1] = f.y; v[i * 4 + 2] = f.z; v[i * 4 + 3] = f.w;
        }
        __half h[32];
#pragma unroll
        for (int t4 = 0; t4 < 4; t4++) {
#pragma unroll
            for (int blk = 0; blk < 2; blk++) {
                int o = t4 * 8 + blk * 4;
                int c = blk * 16 + 2 * t4;
                h[o + 0] = __float2half_rn(v[c + 0]);
                h[o + 1] = __float2half_rn(v[c + 1]);
                h[o + 2] = __float2half_rn(v[c + 8]);
                h[o + 3] = __float2half_rn(v[c + 9]);
            }
        }
#pragma unroll
        for (int i = 0; i < 4; i++)
            ((uint4*)dst)[i] = ((const uint4*)h)[i];
    }

    // ======== grid barrier (sense-reversal; monotonic gen across graph replays) ========
    __threadfence();
    __syncthreads();
    if (tid == 0) {
        unsigned my = atomicAdd(&g_bar_gen, 0u);
        if (atomicAdd(&g_bar_count, 1u) == NBLOCKS - 1u) {
            g_bar_count = 0u;
            __threadfence();
            atomicAdd(&g_bar_gen, 1u);
        } else {
            while (atomicAdd(&g_bar_gen, 0u) == my) { }
        }
    }
    __syncthreads();

    // ======== phase 2: persistent tile loop ========
    float* bias_s = (float*)(smem + SM_BIAS);
    float* gnw_s  = (float*)(smem + SM_GNW);
    float* gnb_s  = (float*)(smem + SM_GNB);
    int rA = tid >> 2, cA = tid & 3;
    uint32_t cpA = sb + SM_A + (uint32_t)(rA * ROWB + cA * 16);
    uint32_t cpB = sb + SM_B + (uint32_t)(rA * ROWB + cA * 16);
    uint32_t aBase = sb + SM_A + (uint32_t)((wm * 64 + gid) * ROWB + tid4 * 16);
    uint32_t bBase = sb + SM_B + (uint32_t)((wn * 64 + gid) * ROWB + tid4 * 16);
#define GCH 262144
#define SCH 4096

    for (int tix = blockIdx.x; tix < NTILES; tix += NBLOCKS) {
        int bn = tix & 15, bm = tix >> 4;

        __syncthreads();                       // smem reuse vs previous tile epilogue
        if (tid < BN) {
            bias_s[tid] = bias[bn * BN + tid];
            gnw_s[tid]  = gnw[bn * BN + tid];
            gnb_s[tid]  = gnb[bn * BN + tid];
        }

        const __half* aPtr = g_xsh + (size_t)bm * BM * KTOT + (size_t)rA * KTOT + cA * 8;
        const __half* bPtr = g_wsh + (size_t)bn * BN * KTOT + (size_t)rA * KTOT + cA * 8;

        // prologue: stages 0..6
#define PRO(p) do {                                                       \
        CP_A16I(cpA, aPtr, (p) * ASTG_A + 0 * SCH, (p) * 64 + 0 * GCH);   \
        CP_A16I(cpA, aPtr, (p) * ASTG_A + 1 * SCH, (p) * 64 + 1 * GCH);   \
        CP_A16I(cpA, aPtr, (p) * ASTG_A + 2 * SCH, (p) * 64 + 2 * GCH);   \
        CP_A16I(cpA, aPtr, (p) * ASTG_A + 3 * SCH, (p) * 64 + 3 * GCH);   \
        CP_A16I(cpB, bPtr, (p) * ASTG_B + 0 * SCH, (p) * 64 + 0 * GCH);   \
        CP_A16I(cpB, bPtr, (p) * ASTG_B + 1 * SCH, (p) * 64 + 1 * GCH);   \
        CP_COMMIT();                                                      \
    } while (0)
        PRO(0); PRO(1); PRO(2); PRO(3); PRO(4); PRO(5); PRO(6);
#undef PRO
        aPtr += (STAGES - 1) * BK;
        bPtr += (STAGES - 1) * BK;

        float acc[4][8][4];
#pragma unroll
        for (int mi = 0; mi < 4; mi++)
#pragma unroll
            for (int ni = 0; ni < 8; ni++)
#pragma unroll
                for (int j = 0; j < 4; j++) acc[mi][ni][j] = 0.f;

#define LD_FRAGS(S)                                                              \
        LDS128I(alo[0][0], alo[0][1], alo[0][2], alo[0][3], aBase,               \
                (S) * ASTG_A + 0 * 1024);                                        \
        LDS128I(ahi[0][0], ahi[0][1], ahi[0][2], ahi[0][3], aBase,               \
                (S) * ASTG_A + 0 * 1024 + 512);                                  \
        LDS128I(alo[1][0], alo[1][1], alo[1][2], alo[1][3], aBase,               \
                (S) * ASTG_A + 1 * 1024);                                        \
        LDS128I(ahi[1][0], ahi[1][1], ahi[1][2], ahi[1][3], aBase,               \
                (S) * ASTG_A + 1 * 1024 + 512);                                  \
        LDS128I(alo[2][0], alo[2][1], alo[2][2], alo[2][3], aBase,               \
                (S) * ASTG_A + 2 * 1024);                                        \
        LDS128I(ahi[2][0], ahi[2][1], ahi[2][2], ahi[2][3], aBase,               \
                (S) * ASTG_A + 2 * 1024 + 512);                                  \
        LDS128I(alo[3][0], alo[3][1], alo[3][2], alo[3][3], aBase,               \
                (S) * ASTG_A + 3 * 1024);                                        \
        LDS128I(ahi[3][0], ahi[3][1], ahi[3][2], ahi[3][3], aBase,               \
                (S) * ASTG_A + 3 * 1024 + 512);                                  \
        LDS128I(bfr[0][0], bfr[0][1], bfr[0][2], bfr[0][3], bBase,               \
                (S) * ASTG_B + 0 * 512);                                         \
        LDS128I(bfr[1][0], bfr[1][1], bfr[1][2], bfr[1][3], bBase,               \
                (S) * ASTG_B + 1 * 512);                                         \
        LDS128I(bfr[2][0], bfr[2][1], bfr[2][2], bfr[2][3], bBase,               \
                (S) * ASTG_B + 2 * 512);                                         \
        LDS128I(bfr[3][0], bfr[3][1], bfr[3][2], bfr[3][3], bBase,               \
                (S) * ASTG_B + 3 * 512);                                         \
        LDS128I(bfr[4][0], bfr[4][1], bfr[4][2], bfr[4][3], bBase,               \
                (S) * ASTG_B + 4 * 512);                                         \
        LDS128I(bfr[5][0], bfr[5][1], bfr[5][2], bfr[5][3], bBase,               \
                (S) * ASTG_B + 5 * 512);                                         \
        LDS128I(bfr[6][0], bfr[6][1], bfr[6][2], bfr[6][3], bBase,               \
                (S) * ASTG_B + 6 * 512);                                         \
        LDS128I(bfr[7][0], bfr[7][1], bfr[7][2], bfr[7][3], bBase,               \
                (S) * ASTG_B + 7 * 512);

#define KITER(S)                                                                 \
    do {                                                                         \
        CP_WAIT(STAGES - 2);                                                     \
        __syncthreads();                                                         \
        if (k0 + (S) + STAGES - 1 < KSTEPS) {                                    \
            constexpr int PS = ((S) + STAGES - 1) & (STAGES - 1);                \
            CP_A16I(cpA, aPtr, PS * ASTG_A + 0 * SCH, (S) * 64 + 0 * GCH);       \
            CP_A16I(cpA, aPtr, PS * ASTG_A + 1 * SCH, (S) * 64 + 1 * GCH);       \
            CP_A16I(cpA, aPtr, PS * ASTG_A + 2 * SCH, (S) * 64 + 2 * GCH);       \
            CP_A16I(cpA, aPtr, PS * ASTG_A + 3 * SCH, (S) * 64 + 3 * GCH);       \
            CP_A16I(cpB, bPtr, PS * ASTG_B + 0 * SCH, (S) * 64 + 0 * GCH);       \
            CP_A16I(cpB, bPtr, PS * ASTG_B + 1 * SCH, (S) * 64 + 1 * GCH);       \
        }                                                                        \
        CP_COMMIT();                                                             \
        uint32_t alo[4][4], ahi[4][4], bfr[8][4];                                \
        LD_FRAGS(S)                                                              \
        _Pragma("unroll")                                                        \
        for (int blk = 0; blk < 2; blk++)                                        \
            _Pragma("unroll")                                                    \
            for (int mi = 0; mi < 4; mi++)                                       \
                _Pragma("unroll")                                                \
                for (int ni = 0; ni < 8; ni++)                                   \
                    mma_f16(acc[mi][ni],                                         \
                            alo[mi][blk * 2 + 0], ahi[mi][blk * 2 + 0],          \
                            alo[mi][blk * 2 + 1], ahi[mi][blk * 2 + 1],          \
                            bfr[ni][blk * 2 + 0], bfr[ni][blk * 2 + 1]);         \
    } while (0)

        for (int k0 = 0; k0 < KSTEPS; k0 += STAGES) {
            KITER(0);
            KITER(1);
            KITER(2);
            KITER(3);
            KITER(4);
            KITER(5);
            KITER(6);
            KITER(7);
            aPtr += STAGES * BK;      // one bump per 8 k-steps
            bPtr += STAGES * BK;
        }
#undef KITER
#undef LD_FRAGS

        // ---- fused epilogue: bias + GroupNorm(64) + hardtanh ----
        int gcol = wn * 64;
        size_t gout = (size_t)bn * BN + gcol;

#pragma unroll
        for (int mi = 0; mi < 4; mi++) {
#pragma unroll
            for (int half = 0; half < 2; half++) {
                int row_l = wm * 64 + mi * 16 + half * 8 + gid;
                float sum = 0.f, ssq = 0.f;
                float v[8][2];
#pragma unroll
                for (int ni = 0; ni < 8; ni++) {
                    int c = ni * 8 + 2 * tid4;
                    float v0 = acc[mi][ni][half * 2 + 0] + bias_s[gcol + c + 0];
                    float v1 = acc[mi][ni][half * 2 + 1] + bias_s[gcol + c + 1];
                    v[ni][0] = v0; v[ni][1] = v1;
                    sum += v0 + v1;
                    ssq += v0 * v0 + v1 * v1;
                }
                sum += __shfl_xor_sync(0xffffffffu, sum, 1);
                ssq += __shfl_xor_sync(0xffffffffu, ssq, 1);
                sum += __shfl_xor_sync(0xffffffffu, sum, 2);
                ssq += __shfl_xor_sync(0xffffffffu, ssq, 2);

                float mean = sum * (1.f / 64.f);
                float var  = ssq * (1.f / 64.f) - mean * mean;
                float inv  = rsqrtf(var + 1e-5f);

                size_t orow = (size_t)(bm * BM + row_l) * NTOT + gout;
#pragma unroll
                for (int ni = 0; ni < 8; ni++) {
                    int c = ni * 8 + 2 * tid4;
                    float2 o;
                    o.x = fminf(fmaxf((v[ni][0] - mean) * inv * gnw_s[gcol + c + 0]
                                      + gnb_s[gcol + c + 0], -1.f), 1.f);
                    o.y = fminf(fmaxf((v[ni][1] - mean) * inv * gnw_s[gcol + c + 1]
                                      + gnb_s[gcol + c + 1], -1.f), 1.f);
                    *(float2*)(out + orow + c) = o;
                }
            }
        }
    }
}

// ---------------- launch ----------------
extern "C" void kernel_launch(void* const* d_in, const int* in_sizes, int n_in,
                              void* d_out, int out_size) {
    const float* x    = (const float*)d_in[0];
    const float* w    = (const float*)d_in[1];
    const float* bias = (const float*)d_in[2];
    const float* gnw  = (const float*)d_in[3];
    const float* gnb  = (const float*)d_in[4];
    float* out = (float*)d_out;

    static bool attr_done = false;
    if (!attr_done) {
        cudaFuncSetAttribute(fused_linear_gn_ht_kernel,
                             cudaFuncAttributeMaxDynamicSharedMemorySize, SMEM_TOTAL);
        attr_done = true;
    }

    fused_linear_gn_ht_kernel<<<NBLOCKS, THREADS, SMEM_TOTAL>>>(x, w, bias, gnw, gnb, out);
}